// round 12
// baseline (speedup 1.0000x reference)
#include <cuda_runtime.h>
#include <math.h>

#define Bq 4
#define Nq 512
#define DIN 128
#define F 64
#define NN (Nq*Nq)
#define ALPHA 0.2f
#define MSPLIT 4
#define MCHUNK (Nq/MSPLIT)     // 128
#define KS 8
#define KC (DIN/KS)            // 16
#define NR (Bq*Nq)             // 2048 rows

// scratch (plain stores; counters rely on modulo so no zeroing needed)
__device__ float g_hpart[(long)KS*NR*F];   // 4MB k-partials
__device__ float g_s1p[KS*NR];
__device__ float g_tp [KS*NR];
__device__ float g_h [NR*F];
__device__ float g_s1[NR];
__device__ float g_t [NR];
__device__ unsigned g_ctrA[NR/16];         // 128 rowblock counters
__device__ float g_part[MSPLIT*NR*F];      // AV partials
__device__ float g_psum[MSPLIT*NR];        // row-sum partials

// ---------------------------------------------------------------------------
// Kernel A: split-k8, MLP-batched, last-of-8 block combines h/s1/t.
// thread=(f4,row). 16 rows x 16 k per block. Grid 1024.
// ---------------------------------------------------------------------------
__global__ __launch_bounds__(256) void gat_h_kernel(
    const float* __restrict__ x, const float* __restrict__ W,
    const float* __restrict__ bias, const float* __restrict__ a)
{
    __shared__ __align__(16) float xs[16*KC];   // 1KB
    __shared__ int lastA;

    int bid  = blockIdx.x;
    int kc   = bid & 7;
    int rb   = bid >> 3;
    int row0 = rb * 16;
    int k0   = kc * KC;

    int tid   = threadIdx.x;
    int f4    = tid & 15;
    int rslot = tid >> 4;
    int row   = row0 + rslot;

    if (tid < 64) {
        int r = tid >> 2, c = tid & 3;
        ((float4*)xs)[tid] = *(const float4*)(x + (long)(row0 + r)*DIN + k0 + c*4);
    }
    __syncthreads();

    // x row into registers (4x LDS.128, MLP 4)
    float4 xv0 = ((const float4*)(xs + rslot*KC))[0];
    float4 xv1 = ((const float4*)(xs + rslot*KC))[1];
    float4 xv2 = ((const float4*)(xs + rslot*KC))[2];
    float4 xv3 = ((const float4*)(xs + rslot*KC))[3];

    const float4* W4 = (const float4*)(W + (long)k0*F);   // [k][16 quads]
    float4 acc = (kc == 0) ? ((const float4*)bias)[f4]
                           : make_float4(0.f, 0.f, 0.f, 0.f);

    // batches of 4 W quads in flight (MLP 4), 16 FFMA per batch
    #pragma unroll
    for (int h = 0; h < 4; ++h) {
        float4 w0 = W4[(h*4+0)*16 + f4];
        float4 w1 = W4[(h*4+1)*16 + f4];
        float4 w2 = W4[(h*4+2)*16 + f4];
        float4 w3 = W4[(h*4+3)*16 + f4];
        float4 xq = (h == 0) ? xv0 : (h == 1) ? xv1 : (h == 2) ? xv2 : xv3;
        acc.x += xq.x*w0.x; acc.y += xq.x*w0.y; acc.z += xq.x*w0.z; acc.w += xq.x*w0.w;
        acc.x += xq.y*w1.x; acc.y += xq.y*w1.y; acc.z += xq.y*w1.z; acc.w += xq.y*w1.w;
        acc.x += xq.z*w2.x; acc.y += xq.z*w2.y; acc.z += xq.z*w2.z; acc.w += xq.z*w2.w;
        acc.x += xq.w*w3.x; acc.y += xq.w*w3.y; acc.z += xq.w*w3.z; acc.w += xq.w*w3.w;
    }

    ((float4*)g_hpart)[((long)kc*NR + row)*16 + f4] = acc;

    float4 a1 = ((const float4*)a)[f4];
    float4 a2 = ((const float4*)a)[16 + f4];
    float s1 = acc.x*a1.x + acc.y*a1.y + acc.z*a1.z + acc.w*a1.w;
    float t  = acc.x*a2.x + acc.y*a2.y + acc.z*a2.z + acc.w*a2.w;
    #pragma unroll
    for (int o = 8; o; o >>= 1) {        // 16-lane row group
        s1 += __shfl_xor_sync(0xffffffffu, s1, o);
        t  += __shfl_xor_sync(0xffffffffu, t,  o);
    }
    if (f4 == 0) {
        g_s1p[kc*NR + row] = s1;
        g_tp [kc*NR + row] = t;
    }

    // ---- last of 8 kc-blocks combines (modulo counter: replay-safe) ----
    __threadfence();                      // release: partials before counter
    if (tid == 0)
        lastA = ((atomicAdd(g_ctrA + rb, 1u) & 7u) == 7u);
    __syncthreads();
    if (lastA) {
        __threadfence();                  // acquire: counter before reads
        const float4* hp = (const float4*)g_hpart;
        long idx = (long)row*16 + f4;
        float4 s = __ldcg(hp + idx);
        #pragma unroll
        for (int kc2 = 1; kc2 < KS; ++kc2) {
            float4 v = __ldcg(hp + (long)kc2*NR*16 + idx);
            s.x += v.x; s.y += v.y; s.z += v.z; s.w += v.w;
        }
        ((float4*)g_h)[idx] = s;

        if (f4 == 0) {
            float sv = 0.f;
            #pragma unroll
            for (int kc2 = 0; kc2 < KS; ++kc2) sv += __ldcg(g_s1p + kc2*NR + row);
            g_s1[row] = sv;
        } else if (f4 == 1) {
            float tv = 0.f;
            #pragma unroll
            for (int kc2 = 0; kc2 < KS; ++kc2) tv += __ldcg(g_tp + kc2*NR + row);
            g_t[row] = tv;
        }
    }
}

// ---------------------------------------------------------------------------
// Kernel B: 8 rows x 128-m chunk per block. 256 threads, grid 1024.
// Fused: masked exp(leakyrelu(logits)) + row sums + partial AV. Plain stores.
// ---------------------------------------------------------------------------
__global__ __launch_bounds__(256) void gat_attn_kernel(const int* __restrict__ adj)
{
    __shared__ float s1s[Nq];
    __shared__ float ts [Nq];
    __shared__ __align__(16) float buf[4096];   // probs[8][128] (4KB) then red (16KB)
    float (*probs)[MCHUNK] = (float(*)[MCHUNK])buf;

    int tid  = threadIdx.x;
    int lane = tid & 31;
    int wid  = tid >> 5;                 // 0..7
    int bid  = blockIdx.x;
    int ms   = bid & 3;
    int rb   = (bid >> 2) & 63;
    int b    = bid >> 8;
    int n0   = rb << 3;
    int m0   = ms * MCHUNK;

    for (int i = tid; i < Nq; i += 256) {
        s1s[i] = g_s1[b*Nq + i];
        ts [i] = g_t [b*Nq + i];
    }
    __syncthreads();

    // ---- phase 1: exp(leakyrelu(logits)) masked, + row partial sums ----
    {
        int n  = n0 + wid;
        int ma = m0 + lane*4;
        const int4 av = *(const int4*)(adj + ((long)b*Nq + n)*Nq + ma);
        int avv[4] = {av.x, av.y, av.z, av.w};
        float4 p4;
        float* pp = (float*)&p4;
        float sum = 0.f;
        #pragma unroll
        for (int j = 0; j < 4; ++j) {
            int m  = ma + j;
            int q1 = 2*(n*Nq + m);
            int idx1 = (q1   < NN) ? (q1   >> 9) : ((q1   - NN) & (Nq-1));
            int idx2 = (q1+1 < NN) ? ((q1+1)>> 9) : ((q1+1 - NN) & (Nq-1));
            float e = s1s[idx1] + ts[idx2];
            e = (e > 0.0f) ? e : ALPHA*e;
            float p = (avv[j] > 0) ? __expf(e) : 0.0f;
            pp[j] = p; sum += p;
        }
        *(float4*)&probs[wid][lane*4] = p4;
        #pragma unroll
        for (int o = 16; o; o >>= 1) sum += __shfl_xor_sync(0xffffffffu, sum, o);
        if (lane == 0) g_psum[(ms*Bq + b)*Nq + n] = sum;
    }
    __syncthreads();

    // ---- phase 2: partial AV. warp = 16 contiguous m, lane = f2 ----
    float2 acc[8];
    #pragma unroll
    for (int r = 0; r < 8; ++r) acc[r] = make_float2(0.f, 0.f);

    const float2* h2 = (const float2*)(g_h + (long)b*Nq*F);
    #pragma unroll
    for (int kcc = 0; kcc < 4; ++kcc) {
        int mloc = wid*16 + kcc*4;
        int mabs = m0 + mloc;
        float2 hv0 = h2[(mabs+0)*32 + lane];
        float2 hv1 = h2[(mabs+1)*32 + lane];
        float2 hv2 = h2[(mabs+2)*32 + lane];
        float2 hv3 = h2[(mabs+3)*32 + lane];
        #pragma unroll
        for (int r = 0; r < 8; ++r) {
            float4 p = *(const float4*)&probs[r][mloc];
            acc[r].x += p.x*hv0.x + p.y*hv1.x + p.z*hv2.x + p.w*hv3.x;
            acc[r].y += p.x*hv0.y + p.y*hv1.y + p.z*hv2.y + p.w*hv3.y;
        }
    }
    __syncthreads();                      // probs dead; buf becomes red (16KB)

    float2* red = (float2*)buf;           // [8 g][8 r][32 f2]
    #pragma unroll
    for (int r = 0; r < 8; ++r)
        red[(wid*8 + r)*32 + lane] = acc[r];
    __syncthreads();

    {
        int r = wid;
        float2 o = make_float2(0.f, 0.f);
        #pragma unroll
        for (int g = 0; g < 8; ++g) {
            float2 v = red[(g*8 + r)*32 + lane];
            o.x += v.x; o.y += v.y;
        }
        ((float2*)g_part)[((long)(ms*Bq + b)*Nq + n0 + r)*32 + lane] = o;
    }
}

// ---------------------------------------------------------------------------
// Kernel C: combine + normalize + elu. Thread = one output element,
// fully coalesced. Grid 512 x 256 thr = 4096 warps.
// ---------------------------------------------------------------------------
__global__ __launch_bounds__(256) void gat_combine_kernel(float* __restrict__ out)
{
    int gid = blockIdx.x*256 + threadIdx.x;   // 0..131071
    int row = gid >> 6;                       // F=64

    float acc = 0.f, s = 0.f;
    #pragma unroll
    for (int ms = 0; ms < MSPLIT; ++ms) {
        acc += g_part[(long)ms*NR*F + gid];
        s   += g_psum[ms*NR + row];
    }
    float v = acc / s;
    out[gid] = (v > 0.0f) ? v : expm1f(v);
}

// ---------------------------------------------------------------------------
extern "C" void kernel_launch(void* const* d_in, const int* in_sizes, int n_in,
                              void* d_out, int out_size)
{
    const float* x    = (const float*)d_in[0];
    const int*   adj  = (const int*)  d_in[1];
    const float* W    = (const float*)d_in[2];
    const float* bias = (const float*)d_in[3];
    const float* a    = (const float*)d_in[4];
    float* out = (float*)d_out;

    gat_h_kernel<<<(NR/16)*KS, 256>>>(x, W, bias, a);
    gat_attn_kernel<<<Bq*64*MSPLIT, 256>>>(adj);
    gat_combine_kernel<<<(NR*F)/256, 256>>>(out);
}

// round 13
// speedup vs baseline: 1.0852x; 1.0852x over previous
#include <cuda_runtime.h>
#include <math.h>

#define Bq 4
#define Nq 512
#define DIN 128
#define F 64
#define NN (Nq*Nq)
#define ALPHA 0.2f
#define MSPLIT 4
#define MCHUNK (Nq/MSPLIT)     // 128
#define KS 8
#define KC (DIN/KS)            // 16
#define NR (Bq*Nq)             // 2048 rows

// scratch (plain stores only)
__device__ float g_hpart[(long)KS*NR*F];   // 4MB h k-partials
__device__ float g_s1p[KS*NR];
__device__ float g_tp [KS*NR];
__device__ float g_h [NR*F];
__device__ float g_s1[NR];
__device__ float g_t [NR];
__device__ float g_part[MSPLIT*NR*F];      // AV partials
__device__ float g_psum[MSPLIT*NR];        // row-sum partials

// ---------------------------------------------------------------------------
// Kernel A: split-k8, vec4. thread=(f4,row). 16 rows x 16 k per block.
// Grid 1024 = 8192 warps. (R8 kernel, measured-best A)
// ---------------------------------------------------------------------------
__global__ __launch_bounds__(256) void gat_h_kernel(
    const float* __restrict__ x, const float* __restrict__ W,
    const float* __restrict__ bias, const float* __restrict__ a)
{
    __shared__ __align__(16) float xs[16*KC];   // 1KB

    int bid  = blockIdx.x;
    int kc   = bid & 7;
    int rb   = bid >> 3;
    int row0 = rb * 16;
    int k0   = kc * KC;

    int tid   = threadIdx.x;
    int f4    = tid & 15;
    int rslot = tid >> 4;
    int row   = row0 + rslot;

    if (tid < 64) {
        int r = tid >> 2, c = tid & 3;
        ((float4*)xs)[tid] = *(const float4*)(x + (long)(row0 + r)*DIN + k0 + c*4);
    }
    __syncthreads();

    const float4* W4 = (const float4*)(W + (long)k0*F);   // [k][16 quads]
    float4 acc = (kc == 0) ? ((const float4*)bias)[f4]
                           : make_float4(0.f, 0.f, 0.f, 0.f);
    const float* xr = xs + rslot*KC;

    #pragma unroll
    for (int k = 0; k < KC; ++k) {
        float4 w  = W4[k*16 + f4];
        float  xk = xr[k];
        acc.x += xk*w.x; acc.y += xk*w.y; acc.z += xk*w.z; acc.w += xk*w.w;
    }

    ((float4*)g_hpart)[((long)kc*NR + row)*16 + f4] = acc;

    float4 a1 = ((const float4*)a)[f4];
    float4 a2 = ((const float4*)a)[16 + f4];
    float s1 = acc.x*a1.x + acc.y*a1.y + acc.z*a1.z + acc.w*a1.w;
    float t  = acc.x*a2.x + acc.y*a2.y + acc.z*a2.z + acc.w*a2.w;
    #pragma unroll
    for (int o = 8; o; o >>= 1) {        // reduce within 16-lane row group
        s1 += __shfl_xor_sync(0xffffffffu, s1, o);
        t  += __shfl_xor_sync(0xffffffffu, t,  o);
    }
    if (f4 == 0) {
        g_s1p[kc*NR + row] = s1;
        g_tp [kc*NR + row] = t;
    }
}

// ---------------------------------------------------------------------------
// Kernel A2: combine 8 k-partials once. float2/thread, 256 blocks x 256 thr
// = 2048 warps (2x R8 warp count).
// ---------------------------------------------------------------------------
__global__ __launch_bounds__(256) void gat_hsum_kernel()
{
    int gid = blockIdx.x*256 + threadIdx.x;   // 0..65535
    int row = gid >> 5;
    int f2  = gid & 31;

    const float2* hp = (const float2*)g_hpart;
    float2 s = make_float2(0.f, 0.f);
    #pragma unroll
    for (int kc = 0; kc < KS; ++kc) {
        float2 v = hp[((long)kc*NR + row)*32 + f2];
        s.x += v.x; s.y += v.y;
    }
    ((float2*)g_h)[(long)row*32 + f2] = s;

    if (gid < NR) {
        float s1 = 0.f, t = 0.f;
        #pragma unroll
        for (int kc = 0; kc < KS; ++kc) {
            s1 += g_s1p[kc*NR + gid];
            t  += g_tp [kc*NR + gid];
        }
        g_s1[gid] = s1;
        g_t [gid] = t;
    }
}

// ---------------------------------------------------------------------------
// Kernel B: 8 rows x 128-m chunk per block. 256 threads, grid 1024.
// Fused: masked exp(leakyrelu(logits)) + row sums + partial AV. (R8 kernel)
// ---------------------------------------------------------------------------
__global__ __launch_bounds__(256) void gat_attn_kernel(const int* __restrict__ adj)
{
    __shared__ float s1s[Nq];
    __shared__ float ts [Nq];
    __shared__ __align__(16) float buf[4096];   // probs[8][128] (4KB) then red (16KB)
    float (*probs)[MCHUNK] = (float(*)[MCHUNK])buf;

    int tid  = threadIdx.x;
    int lane = tid & 31;
    int wid  = tid >> 5;                 // 0..7
    int bid  = blockIdx.x;
    int ms   = bid & 3;
    int rb   = (bid >> 2) & 63;
    int b    = bid >> 8;
    int n0   = rb << 3;
    int m0   = ms * MCHUNK;

    for (int i = tid; i < Nq; i += 256) {
        s1s[i] = g_s1[b*Nq + i];
        ts [i] = g_t [b*Nq + i];
    }
    __syncthreads();

    // ---- phase 1: exp(leakyrelu(logits)) masked, + row partial sums ----
    {
        int n  = n0 + wid;
        int ma = m0 + lane*4;
        const int4 av = *(const int4*)(adj + ((long)b*Nq + n)*Nq + ma);
        int avv[4] = {av.x, av.y, av.z, av.w};
        float4 p4;
        float* pp = (float*)&p4;
        float sum = 0.f;
        #pragma unroll
        for (int j = 0; j < 4; ++j) {
            int m  = ma + j;
            int q1 = 2*(n*Nq + m);
            int idx1 = (q1   < NN) ? (q1   >> 9) : ((q1   - NN) & (Nq-1));
            int idx2 = (q1+1 < NN) ? ((q1+1)>> 9) : ((q1+1 - NN) & (Nq-1));
            float e = s1s[idx1] + ts[idx2];
            e = (e > 0.0f) ? e : ALPHA*e;
            float p = (avv[j] > 0) ? __expf(e) : 0.0f;
            pp[j] = p; sum += p;
        }
        *(float4*)&probs[wid][lane*4] = p4;
        #pragma unroll
        for (int o = 16; o; o >>= 1) sum += __shfl_xor_sync(0xffffffffu, sum, o);
        if (lane == 0) g_psum[(ms*Bq + b)*Nq + n] = sum;
    }
    __syncthreads();

    // ---- phase 2: partial AV. warp = 16 contiguous m, lane = f2 ----
    float2 acc[8];
    #pragma unroll
    for (int r = 0; r < 8; ++r) acc[r] = make_float2(0.f, 0.f);

    const float2* h2 = (const float2*)(g_h + (long)b*Nq*F);
    #pragma unroll
    for (int kcc = 0; kcc < 4; ++kcc) {
        int mloc = wid*16 + kcc*4;
        int mabs = m0 + mloc;
        float2 hv0 = h2[(mabs+0)*32 + lane];
        float2 hv1 = h2[(mabs+1)*32 + lane];
        float2 hv2 = h2[(mabs+2)*32 + lane];
        float2 hv3 = h2[(mabs+3)*32 + lane];
        #pragma unroll
        for (int r = 0; r < 8; ++r) {
            float4 p = *(const float4*)&probs[r][mloc];
            acc[r].x += p.x*hv0.x + p.y*hv1.x + p.z*hv2.x + p.w*hv3.x;
            acc[r].y += p.x*hv0.y + p.y*hv1.y + p.z*hv2.y + p.w*hv3.y;
        }
    }
    __syncthreads();                      // probs dead; buf becomes red (16KB)

    float2* red = (float2*)buf;           // [8 g][8 r][32 f2]
    #pragma unroll
    for (int r = 0; r < 8; ++r)
        red[(wid*8 + r)*32 + lane] = acc[r];
    __syncthreads();

    {
        int r = wid;
        float2 o = make_float2(0.f, 0.f);
        #pragma unroll
        for (int g = 0; g < 8; ++g) {
            float2 v = red[(g*8 + r)*32 + lane];
            o.x += v.x; o.y += v.y;
        }
        ((float2*)g_part)[((long)(ms*Bq + b)*Nq + n0 + r)*32 + lane] = o;
    }
}

// ---------------------------------------------------------------------------
// Kernel C: combine + normalize + elu. Thread = one output element,
// fully coalesced. Grid 512 x 256 thr = 4096 warps. (R11 kernel)
// ---------------------------------------------------------------------------
__global__ __launch_bounds__(256) void gat_combine_kernel(float* __restrict__ out)
{
    int gid = blockIdx.x*256 + threadIdx.x;   // 0..131071
    int row = gid >> 6;                       // F=64

    float acc = 0.f, s = 0.f;
    #pragma unroll
    for (int ms = 0; ms < MSPLIT; ++ms) {
        acc += g_part[(long)ms*NR*F + gid];
        s   += g_psum[ms*NR + row];
    }
    float v = acc / s;
    out[gid] = (v > 0.0f) ? v : expm1f(v);
}

// ---------------------------------------------------------------------------
extern "C" void kernel_launch(void* const* d_in, const int* in_sizes, int n_in,
                              void* d_out, int out_size)
{
    const float* x    = (const float*)d_in[0];
    const int*   adj  = (const int*)  d_in[1];
    const float* W    = (const float*)d_in[2];
    const float* bias = (const float*)d_in[3];
    const float* a    = (const float*)d_in[4];
    float* out = (float*)d_out;

    gat_h_kernel<<<(NR/16)*KS, 256>>>(x, W, bias, a);
    gat_hsum_kernel<<<256, 256>>>();
    gat_attn_kernel<<<Bq*64*MSPLIT, 256>>>(adj);
    gat_combine_kernel<<<(NR*F)/256, 256>>>(out);
}